// round 3
// baseline (speedup 1.0000x reference)
#include <cuda_runtime.h>
#include <cuda_bf16.h>

// Problem constants (fixed shapes from reference)
#define B_ 4
#define S_ 4096
#define D_ 1024
#define F_ 256
#define M_ (B_ * S_)                 // 16384 rows
#define BSD_ (16777216)              // M_ * D_
#define TWOF_ (512)

// -------- scratch (no cudaMalloc allowed; use __device__ globals) --------
// Layout: xn[16M] spec[8M] y[8M] bu[16M] h1[16M] h2[16M] = 80M floats (320MB)
__device__ float g_scratch[83886080];
__device__ double g_errsum;

#define OFF_XN   0L
#define OFF_SPEC 16777216L
#define OFF_Y    25165824L
#define OFF_BU   33554432L
#define OFF_H1   50331648L
#define OFF_H2   67108864L

// -------------------- helpers --------------------
__device__ __forceinline__ float warp_sum(float v) {
#pragma unroll
    for (int o = 16; o; o >>= 1) v += __shfl_xor_sync(0xffffffffu, v, o);
    return v;
}

// -------------------- LayerNorm: one block per row (D=1024, 256 thr x float4) ---
__global__ void __launch_bounds__(256) ln_kernel(const float* __restrict__ x,
                                                 const float* __restrict__ g,
                                                 const float* __restrict__ b,
                                                 float* __restrict__ out) {
    long row = blockIdx.x;
    const float4* xr = (const float4*)(x + row * D_);
    float4* orow = (float4*)(out + row * D_);
    int tid = threadIdx.x;
    float4 v = xr[tid];
    float s = v.x + v.y + v.z + v.w;
    float q = v.x * v.x + v.y * v.y + v.z * v.z + v.w * v.w;
    s = warp_sum(s);
    q = warp_sum(q);
    __shared__ float sh_s[8], sh_q[8];
    int w = tid >> 5, l = tid & 31;
    if (l == 0) { sh_s[w] = s; sh_q[w] = q; }
    __syncthreads();
    if (w == 0) {
        float ss = (l < 8) ? sh_s[l] : 0.f;
        float qq = (l < 8) ? sh_q[l] : 0.f;
        ss = warp_sum(ss);
        qq = warp_sum(qq);
        if (l == 0) { sh_s[0] = ss; sh_q[0] = qq; }
    }
    __syncthreads();
    float mu = sh_s[0] * (1.f / D_);
    float var = sh_q[0] * (1.f / D_) - mu * mu;
    float r = rsqrtf(var + 1e-5f);
    float4 gg = ((const float4*)g)[tid];
    float4 bb = ((const float4*)b)[tid];
    float4 o;
    o.x = (v.x - mu) * r * gg.x + bb.x;
    o.y = (v.y - mu) * r * gg.y + bb.y;
    o.z = (v.z - mu) * r * gg.z + bb.z;
    o.w = (v.w - mu) * r * gg.w + bb.w;
    orow[tid] = o;
}

// -------------------- SGEMM: C[m,n] = sum_k A[m,k] * W[n,k] -------------------
// A row-major [M,K], W row-major [N,K] (both K-contiguous). 128x128 tile, BK=8,
// 256 threads, 8x8 micro-tile. EPI: 0=none, 1=bias+exact gelu, 2=bias only.
template <int EPI>
__global__ void __launch_bounds__(256) sgemm_nt(const float* __restrict__ A,
                                                const float* __restrict__ W,
                                                const float* __restrict__ bias,
                                                float* __restrict__ C,
                                                int N, int K) {
    __shared__ float As[8][128];
    __shared__ float Ws[8][128];
    int tid = threadIdx.x;
    int bm = blockIdx.y * 128;
    int bn = blockIdx.x * 128;
    int lrow = tid >> 1;            // 0..127
    int lcol = (tid & 1) << 2;      // 0 or 4
    const float* Ag = A + (long)(bm + lrow) * K + lcol;
    const float* Wg = W + (long)(bn + lrow) * K + lcol;
    int mo = (tid >> 4) << 3;       // 0..120 step 8
    int no = (tid & 15) << 3;

    float acc[8][8];
#pragma unroll
    for (int i = 0; i < 8; i++)
#pragma unroll
        for (int j = 0; j < 8; j++) acc[i][j] = 0.f;

    for (int k0 = 0; k0 < K; k0 += 8) {
        float4 av = *(const float4*)(Ag + k0);
        float4 wv = *(const float4*)(Wg + k0);
        __syncthreads();
        As[lcol + 0][lrow] = av.x; As[lcol + 1][lrow] = av.y;
        As[lcol + 2][lrow] = av.z; As[lcol + 3][lrow] = av.w;
        Ws[lcol + 0][lrow] = wv.x; Ws[lcol + 1][lrow] = wv.y;
        Ws[lcol + 2][lrow] = wv.z; Ws[lcol + 3][lrow] = wv.w;
        __syncthreads();
#pragma unroll
        for (int k = 0; k < 8; k++) {
            float4 a0 = *(const float4*)&As[k][mo];
            float4 a1 = *(const float4*)&As[k][mo + 4];
            float4 b0 = *(const float4*)&Ws[k][no];
            float4 b1 = *(const float4*)&Ws[k][no + 4];
            float af[8] = {a0.x, a0.y, a0.z, a0.w, a1.x, a1.y, a1.z, a1.w};
            float bf[8] = {b0.x, b0.y, b0.z, b0.w, b1.x, b1.y, b1.z, b1.w};
#pragma unroll
            for (int i = 0; i < 8; i++)
#pragma unroll
                for (int j = 0; j < 8; j++)
                    acc[i][j] = fmaf(af[i], bf[j], acc[i][j]);
        }
    }

    float bvals[8];
    if (EPI >= 1) {
#pragma unroll
        for (int j = 0; j < 8; j++) bvals[j] = bias[bn + no + j];
    }
#pragma unroll
    for (int i = 0; i < 8; i++) {
        float* Cr = C + (long)(bm + mo + i) * N + bn + no;
        float t[8];
#pragma unroll
        for (int j = 0; j < 8; j++) {
            float c = acc[i][j];
            if (EPI >= 1) c += bvals[j];
            if (EPI == 1) c = 0.5f * c * (1.f + erff(c * 0.70710678118654752f));
            t[j] = c;
        }
        *(float4*)&Cr[0] = make_float4(t[0], t[1], t[2], t[3]);
        *(float4*)&Cr[4] = make_float4(t[4], t[5], t[6], t[7]);
    }
}

// -------------------- SSM scan (replaces FFT convolution) --------------------
// y[t] = A*y[t-1] + rot*u[t], A = sigmoid(log_decay)*e^{i omega}, |A| < 0.5.
// Chunked with 64-step warm-up halo: truncation error <= |A|^64 < 1e-19.
__global__ void __launch_bounds__(256) scan_kernel(const float* __restrict__ spec,
                                                   const float* __restrict__ log_decay,
                                                   const float* __restrict__ freqs,
                                                   float* __restrict__ y) {
    const int CHUNK = 256, HALO = 64, NCH = S_ / CHUNK;   // 16 chunks
    int id = blockIdx.x * blockDim.x + threadIdx.x;       // 16384 threads
    int f = id & (F_ - 1);
    int chunk = (id >> 8) & (NCH - 1);
    int b = id >> 12;

    float decay = 1.f / (1.f + expf(-log_decay[f]));
    float om = tanhf(freqs[f]) * 0.1f;
    float rr = cosf(om), ri = sinf(om);
    float Ar = decay * rr, Ai = decay * ri;

    int c0 = chunk * CHUNK;
    int c1 = c0 + CHUNK;
    int t0 = c0 - HALO; if (t0 < 0) t0 = 0;

    const float* base = spec + (long)b * S_ * TWOF_;
    float* ybase = y + (long)b * S_ * TWOF_;

    float yr = 0.f, yi = 0.f;
    for (int t = t0; t < c1; ++t) {
        float ur = base[(long)t * TWOF_ + f];
        float ui = base[(long)t * TWOF_ + F_ + f];
        float nyr = Ar * yr - Ai * yi + rr * ur - ri * ui;
        float nyi = Ar * yi + Ai * yr + rr * ui + ri * ur;
        yr = nyr; yi = nyi;
        if (t >= c0) {
            ybase[(long)t * TWOF_ + f] = yr;
            ybase[(long)t * TWOF_ + F_ + f] = yi;
        }
    }
}

// -------------------- error / corrected fusion + mean(e^2) reduction ---------
__global__ void zero_err_kernel() { g_errsum = 0.0; }

__global__ void __launch_bounds__(256) err_kernel(const float4* __restrict__ bu,
                                                  const float4* __restrict__ td,
                                                  const float* __restrict__ ewp,
                                                  float4* __restrict__ corr) {
    int i = blockIdx.x * 256 + threadIdx.x;   // BSD/4 = 4,194,304 float4s
    float s = 1.f / (1.f + expf(-ewp[0]));
    float4 a = bu[i], t = td[i];
    float ex = fminf(fmaxf(a.x - t.x, -1.f), 1.f);
    float ey = fminf(fmaxf(a.y - t.y, -1.f), 1.f);
    float ez = fminf(fmaxf(a.z - t.z, -1.f), 1.f);
    float ew = fminf(fmaxf(a.w - t.w, -1.f), 1.f);
    float4 c;
    c.x = a.x - s * ex; c.y = a.y - s * ey;
    c.z = a.z - s * ez; c.w = a.w - s * ew;
    corr[i] = c;
    float le = ex * ex + ey * ey + ez * ez + ew * ew;
    le = warp_sum(le);
    __shared__ float sh[8];
    int w = threadIdx.x >> 5, l = threadIdx.x & 31;
    if (l == 0) sh[w] = le;
    __syncthreads();
    if (threadIdx.x == 0) {
        float t2 = 0.f;
#pragma unroll
        for (int k = 0; k < 8; k++) t2 += sh[k];
        atomicAdd(&g_errsum, (double)t2);
    }
}

__global__ void fin_kernel(float* __restrict__ out) {
    double m = g_errsum * (1.0 / (double)BSD_);
    float v = (float)m;
    out[2L * BSD_] = fminf(fmaxf(v, 0.f), 1.f);
}

// -------------------- launch --------------------
extern "C" void kernel_launch(void* const* d_in, const int* in_sizes, int n_in,
                              void* d_out, int out_size) {
    const float* bu_in   = (const float*)d_in[0];
    const float* td      = (const float*)d_in[1];
    const float* Wspec   = (const float*)d_in[2];
    const float* logdec  = (const float*)d_in[3];
    const float* freqs   = (const float*)d_in[4];
    const float* Wfrom   = (const float*)d_in[5];
    const float* ln1g    = (const float*)d_in[6];
    const float* ln1b    = (const float*)d_in[7];
    const float* W1      = (const float*)d_in[8];
    const float* b1      = (const float*)d_in[9];
    const float* W2      = (const float*)d_in[10];
    const float* b2      = (const float*)d_in[11];
    const float* ln2g    = (const float*)d_in[12];
    const float* ln2b    = (const float*)d_in[13];
    const float* ewt     = (const float*)d_in[14];
    float* out = (float*)d_out;

    void* sp;
    cudaGetSymbolAddress(&sp, g_scratch);
    float* S0   = (float*)sp;
    float* xn   = S0 + OFF_XN;
    float* spec = S0 + OFF_SPEC;
    float* yv   = S0 + OFF_Y;
    float* buv  = S0 + OFF_BU;
    float* h1   = S0 + OFF_H1;
    float* h2   = S0 + OFF_H2;
    float* corrected = out;           // output 0: [B,S,D]
    float* nextp = out + BSD_;        // output 1: [B,S,D]
                                      // output 2: scalar at out[2*BSD_]

    // 1. ln1(bottom_up) -> xn
    ln_kernel<<<M_, 256>>>(bu_in, ln1g, ln1b, xn);
    // 2. spectral = xn @ W_spec^T  [16384,512]
    sgemm_nt<0><<<dim3(4, 128), 256>>>(xn, Wspec, nullptr, spec, 512, 1024);
    // 3. SSM scan (== FFT causal conv) -> y [16384,512]
    scan_kernel<<<64, 256>>>(spec, logdec, freqs, yv);
    // 4. bu_repr = y @ W_from^T  [16384,1024]
    sgemm_nt<0><<<dim3(8, 128), 256>>>(yv, Wfrom, nullptr, buv, 1024, 512);
    // 5. error/corrected + mean(e^2)
    zero_err_kernel<<<1, 1>>>();
    err_kernel<<<16384, 256>>>((const float4*)buv, (const float4*)td, ewt,
                               (float4*)corrected);
    fin_kernel<<<1, 1>>>(out);
    // 6. h1 = gelu(corrected @ W1^T + b1)
    sgemm_nt<1><<<dim3(8, 128), 256>>>(corrected, W1, b1, h1, 1024, 1024);
    // 7. h2 = h1 @ W2^T + b2
    sgemm_nt<2><<<dim3(8, 128), 256>>>(h1, W2, b2, h2, 1024, 1024);
    // 8. next_prediction = ln2(h2)
    ln_kernel<<<M_, 256>>>(h2, ln2g, ln2b, nextp);
}

// round 10
// speedup vs baseline: 2.0952x; 2.0952x over previous
#include <cuda_runtime.h>
#include <cuda_bf16.h>
#include <cstdint>

// Problem constants (fixed shapes)
#define B_ 4
#define S_ 4096
#define D_ 1024
#define F_ 256
#define M_ 16384
#define BSD_ 16777216L
#define TWOF_ 512

// -------- scratch (no cudaMalloc allowed) --------
// 48M floats = 192MB, regions aliased through the dataflow.
__device__ float g_scratch[50331648];
__device__ __nv_bfloat16 g_wbuf[6291456];   // hi/lo bf16 weights (12MB)
__device__ double g_errsum;

// ==================== helpers ====================
__device__ __forceinline__ float warp_sum(float v) {
#pragma unroll
    for (int o = 16; o; o >>= 1) v += __shfl_xor_sync(0xffffffffu, v, o);
    return v;
}

__device__ __forceinline__ uint32_t smem_u32(const void* p) {
    uint32_t a;
    asm("{ .reg .u64 t; cvta.to.shared.u64 t, %1; cvt.u32.u64 %0, t; }"
        : "=r"(a) : "l"(p));
    return a;
}

// split a,b into bf16 hi + bf16 lo pairs (packed bf16x2 words)
__device__ __forceinline__ void split2(float a, float b, uint32_t& h, uint32_t& l) {
    __nv_bfloat162 hh = __floats2bfloat162_rn(a, b);
    float ra = a - __low2float(hh);
    float rb = b - __high2float(hh);
    __nv_bfloat162 ll = __floats2bfloat162_rn(ra, rb);
    h = *reinterpret_cast<uint32_t*>(&hh);
    l = *reinterpret_cast<uint32_t*>(&ll);
}

#define LDSM4(r0, r1, r2, r3, a) \
    asm volatile("ldmatrix.sync.aligned.m8n8.x4.shared.b16 {%0,%1,%2,%3}, [%4];" \
                 : "=r"(r0), "=r"(r1), "=r"(r2), "=r"(r3) : "r"(a))

#define MMA_BF16(d, a, b) \
    asm volatile("mma.sync.aligned.m16n8k16.row.col.f32.bf16.bf16.f32 " \
                 "{%0,%1,%2,%3}, {%4,%5,%6,%7}, {%8,%9}, {%0,%1,%2,%3};" \
                 : "+f"((d)[0]), "+f"((d)[1]), "+f"((d)[2]), "+f"((d)[3]) \
                 : "r"((a)[0]), "r"((a)[1]), "r"((a)[2]), "r"((a)[3]), \
                   "r"((b)[0]), "r"((b)[1]))

#define CP_ASYNC16(s, g) \
    asm volatile("cp.async.cg.shared.global [%0], [%1], 16;" :: "r"(s), "l"(g))

// ==================== LayerNorm (f32 out, final) ====================
__global__ void __launch_bounds__(256) ln_kernel(const float* __restrict__ x,
                                                 const float* __restrict__ g,
                                                 const float* __restrict__ b,
                                                 float* __restrict__ out) {
    long row = blockIdx.x;
    const float4* xr = (const float4*)(x + row * D_);
    float4* orow = (float4*)(out + row * D_);
    int tid = threadIdx.x;
    float4 v = xr[tid];
    float s = v.x + v.y + v.z + v.w;
    float q = v.x * v.x + v.y * v.y + v.z * v.z + v.w * v.w;
    s = warp_sum(s);
    q = warp_sum(q);
    __shared__ float sh_s[8], sh_q[8];
    int w = tid >> 5, l = tid & 31;
    if (l == 0) { sh_s[w] = s; sh_q[w] = q; }
    __syncthreads();
    if (w == 0) {
        float ss = (l < 8) ? sh_s[l] : 0.f;
        float qq = (l < 8) ? sh_q[l] : 0.f;
        ss = warp_sum(ss);
        qq = warp_sum(qq);
        if (l == 0) { sh_s[0] = ss; sh_q[0] = qq; }
    }
    __syncthreads();
    float mu = sh_s[0] * (1.f / D_);
    float var = sh_q[0] * (1.f / D_) - mu * mu;
    float r = rsqrtf(var + 1e-5f);
    float4 gg = ((const float4*)g)[tid];
    float4 bb = ((const float4*)b)[tid];
    float4 o;
    o.x = (v.x - mu) * r * gg.x + bb.x;
    o.y = (v.y - mu) * r * gg.y + bb.y;
    o.z = (v.z - mu) * r * gg.z + bb.z;
    o.w = (v.w - mu) * r * gg.w + bb.w;
    orow[tid] = o;
}

// ==================== LayerNorm with bf16 hi/lo split output ====================
__global__ void __launch_bounds__(256) ln_split_kernel(const float* __restrict__ x,
                                                       const float* __restrict__ g,
                                                       const float* __restrict__ b,
                                                       __nv_bfloat16* __restrict__ hi,
                                                       __nv_bfloat16* __restrict__ lo) {
    long row = blockIdx.x;
    const float4* xr = (const float4*)(x + row * D_);
    int tid = threadIdx.x;
    float4 v = xr[tid];
    float s = v.x + v.y + v.z + v.w;
    float q = v.x * v.x + v.y * v.y + v.z * v.z + v.w * v.w;
    s = warp_sum(s);
    q = warp_sum(q);
    __shared__ float sh_s[8], sh_q[8];
    int w = tid >> 5, l = tid & 31;
    if (l == 0) { sh_s[w] = s; sh_q[w] = q; }
    __syncthreads();
    if (w == 0) {
        float ss = (l < 8) ? sh_s[l] : 0.f;
        float qq = (l < 8) ? sh_q[l] : 0.f;
        ss = warp_sum(ss);
        qq = warp_sum(qq);
        if (l == 0) { sh_s[0] = ss; sh_q[0] = qq; }
    }
    __syncthreads();
    float mu = sh_s[0] * (1.f / D_);
    float var = sh_q[0] * (1.f / D_) - mu * mu;
    float r = rsqrtf(var + 1e-5f);
    float4 gg = ((const float4*)g)[tid];
    float4 bb = ((const float4*)b)[tid];
    float o0 = (v.x - mu) * r * gg.x + bb.x;
    float o1 = (v.y - mu) * r * gg.y + bb.y;
    float o2 = (v.z - mu) * r * gg.z + bb.z;
    float o3 = (v.w - mu) * r * gg.w + bb.w;
    uint32_t h01, l01, h23, l23;
    split2(o0, o1, h01, l01);
    split2(o2, o3, h23, l23);
    ((uint2*)(hi + row * D_))[tid] = make_uint2(h01, h23);
    ((uint2*)(lo + row * D_))[tid] = make_uint2(l01, l23);
}

// ==================== weight split ====================
__global__ void __launch_bounds__(256) split_kernel(const float4* __restrict__ in,
                                                    uint2* __restrict__ hi,
                                                    uint2* __restrict__ lo, int n4) {
    int i = blockIdx.x * 256 + threadIdx.x;
    if (i >= n4) return;
    float4 v = in[i];
    uint32_t h01, l01, h23, l23;
    split2(v.x, v.y, h01, l01);
    split2(v.z, v.w, h23, l23);
    hi[i] = make_uint2(h01, h23);
    lo[i] = make_uint2(l01, l23);
}

// ==================== bf16-split warp-MMA GEMM ====================
// C[m,n] = sum_k A[m,k]*W[n,k];  A,W given as bf16 hi/lo pairs.
// 128x128x32 tile, 256 thr, 8 warps (4m x 2n), 4-stage cp.async.
// EPI: 0 = f32 out, 1 = bias+gelu -> bf16 hi/lo out, 2 = bias -> f32 out.
#define NSTAGE 4
#define PART_B 10240                  // 128 rows * 80B padded
#define STAGE_BYTES 40960             // AHI ALO BHI BLO
#define SMEM_GEMM (NSTAGE * STAGE_BYTES)

template <int EPI>
__global__ void __launch_bounds__(256, 1) gemm_mma(
    const __nv_bfloat16* __restrict__ Ahi, const __nv_bfloat16* __restrict__ Alo,
    const __nv_bfloat16* __restrict__ Bhi, const __nv_bfloat16* __restrict__ Blo,
    const float* __restrict__ bias,
    float* __restrict__ Cf,
    __nv_bfloat16* __restrict__ Chi, __nv_bfloat16* __restrict__ Clo,
    int N, int K) {
    extern __shared__ char sm[];
    const int tid = threadIdx.x;
    const int lane = tid & 31, w = tid >> 5;
    const int bm = blockIdx.y << 7, bn = blockIdx.x << 7;
    const int wm = (w & 3) << 5, wn = (w >> 2) << 6;
    const uint32_t sbase = smem_u32(sm);

    float acc[2][8][4];
#pragma unroll
    for (int i = 0; i < 2; i++)
#pragma unroll
        for (int j = 0; j < 8; j++)
#pragma unroll
            for (int r = 0; r < 4; r++) acc[i][j][r] = 0.f;

    auto issue = [&](int kt, int s) {
        const int k0 = kt << 5;
        const uint32_t sst = sbase + s * STAGE_BYTES;
#pragma unroll
        for (int p = 0; p < 4; ++p) {
            const __nv_bfloat16* base = (p == 0) ? Ahi : (p == 1) ? Alo
                                      : (p == 2) ? Bhi : Blo;
            const int rb = (p >= 2) ? bn : bm;
#pragma unroll
            for (int i = 0; i < 2; ++i) {
                int ch = tid + (i << 8);          // 0..511
                int row = ch >> 2, c = ch & 3;
                const void* g = base + (long)(rb + row) * K + k0 + (c << 3);
                uint32_t sa = sst + p * PART_B + row * 80 + (c << 4);
                CP_ASYNC16(sa, g);
            }
        }
        asm volatile("cp.async.commit_group;");
    };

    const int nk = K >> 5;
    issue(0, 0); issue(1, 1); issue(2, 2);

    // per-thread ldmatrix row/kc components
    const int lr = lane & 15;          // row within 16-row group
    const int lkc = (lane >> 4) << 4;  // 0 or 16 bytes (k-halves)

    for (int kt = 0; kt < nk; ++kt) {
        asm volatile("cp.async.wait_group 2;");
        __syncthreads();
        int nxt = kt + NSTAGE - 1;
        if (nxt < nk) issue(nxt, nxt & 3);
        else asm volatile("cp.async.commit_group;");

        const uint32_t sst = sbase + (kt & 3) * STAGE_BYTES;
#pragma unroll
        for (int ks = 0; ks < 2; ++ks) {
            uint32_t ah[2][4], al[2][4], bh[8][2], bl[8][2];
#pragma unroll
            for (int mf = 0; mf < 2; ++mf) {
                uint32_t ad = sst + (wm + (mf << 4) + lr) * 80 + (ks << 5) + lkc;
                LDSM4(ah[mf][0], ah[mf][1], ah[mf][2], ah[mf][3], ad);
                LDSM4(al[mf][0], al[mf][1], al[mf][2], al[mf][3], ad + PART_B);
            }
#pragma unroll
            for (int g = 0; g < 4; ++g) {
                uint32_t bd = sst + 2 * PART_B + (wn + (g << 4) + lr) * 80 +
                              (ks << 5) + lkc;
                uint32_t t0, t1, t2, t3;
                LDSM4(t0, t1, t2, t3, bd);
                bh[2 * g][0] = t0; bh[2 * g][1] = t2;
                bh[2 * g + 1][0] = t1; bh[2 * g + 1][1] = t3;
                LDSM4(t0, t1, t2, t3, bd + PART_B);
                bl[2 * g][0] = t0; bl[2 * g][1] = t2;
                bl[2 * g + 1][0] = t1; bl[2 * g + 1][1] = t3;
            }
            // hh, hl, lh — same-acc MMAs 16 apart to hide HMMA latency
#pragma unroll
            for (int mf = 0; mf < 2; ++mf)
#pragma unroll
                for (int nf = 0; nf < 8; ++nf) MMA_BF16(acc[mf][nf], ah[mf], bh[nf]);
#pragma unroll
            for (int mf = 0; mf < 2; ++mf)
#pragma unroll
                for (int nf = 0; nf < 8; ++nf) MMA_BF16(acc[mf][nf], ah[mf], bl[nf]);
#pragma unroll
            for (int mf = 0; mf < 2; ++mf)
#pragma unroll
                for (int nf = 0; nf < 8; ++nf) MMA_BF16(acc[mf][nf], al[mf], bh[nf]);
        }
    }

    // epilogue (register -> gmem)
#pragma unroll
    for (int mf = 0; mf < 2; ++mf) {
#pragma unroll
        for (int h = 0; h < 2; ++h) {
            int row = bm + wm + (mf << 4) + (lane >> 2) + (h << 3);
#pragma unroll
            for (int nf = 0; nf < 8; ++nf) {
                int col = bn + wn + (nf << 3) + ((lane & 3) << 1);
                float v0 = acc[mf][nf][h * 2];
                float v1 = acc[mf][nf][h * 2 + 1];
                if (EPI >= 1) { v0 += bias[col]; v1 += bias[col + 1]; }
                if (EPI == 1) {
                    v0 = 0.5f * v0 * (1.f + erff(v0 * 0.70710678118654752f));
                    v1 = 0.5f * v1 * (1.f + erff(v1 * 0.70710678118654752f));
                    uint32_t hh, ll;
                    split2(v0, v1, hh, ll);
                    *(uint32_t*)(Chi + (long)row * N + col) = hh;
                    *(uint32_t*)(Clo + (long)row * N + col) = ll;
                } else {
                    *(float2*)(Cf + (long)row * N + col) = make_float2(v0, v1);
                }
            }
        }
    }
}

// ==================== SSM scan (== FFT conv; |A|<0.5, halo=64) ====================
__global__ void __launch_bounds__(256) scan_kernel(const float* __restrict__ spec,
                                                   const float* __restrict__ log_decay,
                                                   const float* __restrict__ freqs,
                                                   __nv_bfloat16* __restrict__ yhi,
                                                   __nv_bfloat16* __restrict__ ylo) {
    const int CHUNK = 256, HALO = 64, NCH = S_ / CHUNK;
    int id = blockIdx.x * blockDim.x + threadIdx.x;
    int f = id & (F_ - 1);
    int chunk = (id >> 8) & (NCH - 1);
    int b = id >> 12;

    float decay = 1.f / (1.f + expf(-log_decay[f]));
    float om = tanhf(freqs[f]) * 0.1f;
    float rr = cosf(om), ri = sinf(om);
    float Ar = decay * rr, Ai = decay * ri;

    int c0 = chunk * CHUNK, c1 = c0 + CHUNK;
    int t0 = c0 - HALO; if (t0 < 0) t0 = 0;

    const float* base = spec + (long)b * S_ * TWOF_;
    long ybase = (long)b * S_ * TWOF_;

    float yr = 0.f, yi = 0.f;
    for (int t = t0; t < c1; ++t) {
        float ur = base[(long)t * TWOF_ + f];
        float ui = base[(long)t * TWOF_ + F_ + f];
        float nyr = Ar * yr - Ai * yi + rr * ur - ri * ui;
        float nyi = Ar * yi + Ai * yr + rr * ui + ri * ur;
        yr = nyr; yi = nyi;
        if (t >= c0) {
            long ir = ybase + (long)t * TWOF_ + f;
            long ii = ir + F_;
            __nv_bfloat16 hr = __float2bfloat16_rn(yr);
            __nv_bfloat16 hi2 = __float2bfloat16_rn(yi);
            yhi[ir] = hr; ylo[ir] = __float2bfloat16_rn(yr - __bfloat162float(hr));
            yhi[ii] = hi2; ylo[ii] = __float2bfloat16_rn(yi - __bfloat162float(hi2));
        }
    }
}

// ==================== error / corrected fusion ====================
__global__ void zero_err_kernel() { g_errsum = 0.0; }

__global__ void __launch_bounds__(256) err_kernel(const float4* __restrict__ bu,
                                                  const float4* __restrict__ td,
                                                  const float* __restrict__ ewp,
                                                  float4* __restrict__ corr,
                                                  uint2* __restrict__ chi,
                                                  uint2* __restrict__ clo) {
    int i = blockIdx.x * 256 + threadIdx.x;
    float s = 1.f / (1.f + expf(-ewp[0]));
    float4 a = bu[i], t = td[i];
    float ex = fminf(fmaxf(a.x - t.x, -1.f), 1.f);
    float ey = fminf(fmaxf(a.y - t.y, -1.f), 1.f);
    float ez = fminf(fmaxf(a.z - t.z, -1.f), 1.f);
    float ew = fminf(fmaxf(a.w - t.w, -1.f), 1.f);
    float4 c;
    c.x = a.x - s * ex; c.y = a.y - s * ey;
    c.z = a.z - s * ez; c.w = a.w - s * ew;
    corr[i] = c;
    uint32_t h01, l01, h23, l23;
    split2(c.x, c.y, h01, l01);
    split2(c.z, c.w, h23, l23);
    chi[i] = make_uint2(h01, h23);
    clo[i] = make_uint2(l01, l23);
    float le = ex * ex + ey * ey + ez * ez + ew * ew;
    le = warp_sum(le);
    __shared__ float sh[8];
    int w = threadIdx.x >> 5, l = threadIdx.x & 31;
    if (l == 0) sh[w] = le;
    __syncthreads();
    if (threadIdx.x == 0) {
        float t2 = 0.f;
#pragma unroll
        for (int k = 0; k < 8; k++) t2 += sh[k];
        atomicAdd(&g_errsum, (double)t2);
    }
}

__global__ void fin_kernel(float* __restrict__ out) {
    double m = g_errsum * (1.0 / (double)BSD_);
    float v = (float)m;
    out[2L * BSD_] = fminf(fmaxf(v, 0.f), 1.f);
}

// ==================== launch ====================
extern "C" void kernel_launch(void* const* d_in, const int* in_sizes, int n_in,
                              void* d_out, int out_size) {
    const float* bu_in  = (const float*)d_in[0];
    const float* td     = (const float*)d_in[1];
    const float* Wspec  = (const float*)d_in[2];
    const float* logdec = (const float*)d_in[3];
    const float* freqs  = (const float*)d_in[4];
    const float* Wfrom  = (const float*)d_in[5];
    const float* ln1g   = (const float*)d_in[6];
    const float* ln1b   = (const float*)d_in[7];
    const float* W1     = (const float*)d_in[8];
    const float* b1     = (const float*)d_in[9];
    const float* W2     = (const float*)d_in[10];
    const float* b2     = (const float*)d_in[11];
    const float* ln2g   = (const float*)d_in[12];
    const float* ln2b   = (const float*)d_in[13];
    const float* ewt    = (const float*)d_in[14];
    float* out = (float*)d_out;

    void* sp; cudaGetSymbolAddress(&sp, g_scratch);
    void* wp; cudaGetSymbolAddress(&wp, g_wbuf);
    float* S0 = (float*)sp;
    __nv_bfloat16* WB = (__nv_bfloat16*)wp;

    // region A [0,16M): xn hi/lo, later corr hi/lo
    __nv_bfloat16* xnhi = (__nv_bfloat16*)(S0);
    __nv_bfloat16* xnlo = (__nv_bfloat16*)(S0 + 8388608L);
    // region B [16M,24M): spec f32, later h1hi
    float* spec = S0 + 16777216L;
    __nv_bfloat16* h1hi = (__nv_bfloat16*)(S0 + 16777216L);
    // region C [24M,32M): y hi/lo, later h1lo
    __nv_bfloat16* yhi = (__nv_bfloat16*)(S0 + 25165824L);
    __nv_bfloat16* ylo = (__nv_bfloat16*)(S0 + 29360128L);
    __nv_bfloat16* h1lo = (__nv_bfloat16*)(S0 + 25165824L);
    // region D [32M,48M): buv f32, later h2 f32
    float* buv = S0 + 33554432L;
    float* h2  = S0 + 33554432L;

    // weight hi/lo slots
    __nv_bfloat16* wspechi = WB;
    __nv_bfloat16* wspeclo = WB + 524288L;
    __nv_bfloat16* wfromhi = WB + 1048576L;
    __nv_bfloat16* wfromlo = WB + 1572864L;
    __nv_bfloat16* w1hi    = WB + 2097152L;
    __nv_bfloat16* w1lo    = WB + 3145728L;
    __nv_bfloat16* w2hi    = WB + 4194304L;
    __nv_bfloat16* w2lo    = WB + 5242880L;

    float* corrected = out;
    float* nextp = out + BSD_;

    cudaFuncSetAttribute(gemm_mma<0>, cudaFuncAttributeMaxDynamicSharedMemorySize, SMEM_GEMM);
    cudaFuncSetAttribute(gemm_mma<1>, cudaFuncAttributeMaxDynamicSharedMemorySize, SMEM_GEMM);
    cudaFuncSetAttribute(gemm_mma<2>, cudaFuncAttributeMaxDynamicSharedMemorySize, SMEM_GEMM);

    // weight splits (cheap, every launch for determinism)
    split_kernel<<<512, 256>>>((const float4*)Wspec, (uint2*)wspechi, (uint2*)wspeclo, 131072);
    split_kernel<<<512, 256>>>((const float4*)Wfrom, (uint2*)wfromhi, (uint2*)wfromlo, 131072);
    split_kernel<<<1024, 256>>>((const float4*)W1, (uint2*)w1hi, (uint2*)w1lo, 262144);
    split_kernel<<<1024, 256>>>((const float4*)W2, (uint2*)w2hi, (uint2*)w2lo, 262144);

    // 1. ln1 -> xn hi/lo
    ln_split_kernel<<<M_, 256>>>(bu_in, ln1g, ln1b, xnhi, xnlo);
    // 2. spectral = xn @ Wspec^T [16384,512], K=1024
    gemm_mma<0><<<dim3(4, 128), 256, SMEM_GEMM>>>(xnhi, xnlo, wspechi, wspeclo,
                                                  nullptr, spec, nullptr, nullptr,
                                                  512, 1024);
    // 3. scan -> y hi/lo
    scan_kernel<<<64, 256>>>(spec, logdec, freqs, yhi, ylo);
    // 4. bu_repr = y @ Wfrom^T [16384,1024], K=512
    gemm_mma<0><<<dim3(8, 128), 256, SMEM_GEMM>>>(yhi, ylo, wfromhi, wfromlo,
                                                  nullptr, buv, nullptr, nullptr,
                                                  1024, 512);
    // 5. error/corrected + mean(e^2), corr hi/lo for next GEMM
    zero_err_kernel<<<1, 1>>>();
    err_kernel<<<16384, 256>>>((const float4*)buv, (const float4*)td, ewt,
                               (float4*)corrected, (uint2*)xnhi, (uint2*)xnlo);
    fin_kernel<<<1, 1>>>(out);
    // 6. h1 = gelu(corr @ W1^T + b1) -> bf16 hi/lo
    gemm_mma<1><<<dim3(8, 128), 256, SMEM_GEMM>>>(xnhi, xnlo, w1hi, w1lo, b1,
                                                  nullptr, h1hi, h1lo, 1024, 1024);
    // 7. h2 = h1 @ W2^T + b2 -> f32
    gemm_mma<2><<<dim3(8, 128), 256, SMEM_GEMM>>>(h1hi, h1lo, w2hi, w2lo, b2,
                                                  h2, nullptr, nullptr, 1024, 1024);
    // 8. next_prediction = ln2(h2)
    ln_kernel<<<M_, 256>>>(h2, ln2g, ln2b, nextp);
}

// round 11
// speedup vs baseline: 2.1382x; 1.0205x over previous
#include <cuda_runtime.h>
#include <cuda_bf16.h>
#include <cstdint>

// Problem constants (fixed shapes)
#define B_ 4
#define S_ 4096
#define D_ 1024
#define F_ 256
#define M_ 16384
#define BSD_ 16777216L
#define TWOF_ 512

// -------- scratch (no cudaMalloc allowed) --------
__device__ float g_scratch[50331648];
__device__ __nv_bfloat16 g_wbuf[6291456];   // hi/lo bf16 weights (12MB)
__device__ double g_errsum;

// ==================== helpers ====================
__device__ __forceinline__ float warp_sum(float v) {
#pragma unroll
    for (int o = 16; o; o >>= 1) v += __shfl_xor_sync(0xffffffffu, v, o);
    return v;
}

__device__ __forceinline__ uint32_t smem_u32(const void* p) {
    uint32_t a;
    asm("{ .reg .u64 t; cvta.to.shared.u64 t, %1; cvt.u32.u64 %0, t; }"
        : "=r"(a) : "l"(p));
    return a;
}

__device__ __forceinline__ void split2(float a, float b, uint32_t& h, uint32_t& l) {
    __nv_bfloat162 hh = __floats2bfloat162_rn(a, b);
    float ra = a - __low2float(hh);
    float rb = b - __high2float(hh);
    __nv_bfloat162 ll = __floats2bfloat162_rn(ra, rb);
    h = *reinterpret_cast<uint32_t*>(&hh);
    l = *reinterpret_cast<uint32_t*>(&ll);
}

#define LDSM4(r0, r1, r2, r3, a) \
    asm volatile("ldmatrix.sync.aligned.m8n8.x4.shared.b16 {%0,%1,%2,%3}, [%4];" \
                 : "=r"(r0), "=r"(r1), "=r"(r2), "=r"(r3) : "r"(a))

#define MMA_BF16(d, a, b) \
    asm volatile("mma.sync.aligned.m16n8k16.row.col.f32.bf16.bf16.f32 " \
                 "{%0,%1,%2,%3}, {%4,%5,%6,%7}, {%8,%9}, {%0,%1,%2,%3};" \
                 : "+f"((d)[0]), "+f"((d)[1]), "+f"((d)[2]), "+f"((d)[3]) \
                 : "r"((a)[0]), "r"((a)[1]), "r"((a)[2]), "r"((a)[3]), \
                   "r"((b)[0]), "r"((b)[1]))

#define CP_ASYNC16(s, g) \
    asm volatile("cp.async.cg.shared.global [%0], [%1], 16;" :: "r"(s), "l"(g))

// ==================== LayerNorm (f32 out) ====================
__global__ void __launch_bounds__(256) ln_kernel(const float* __restrict__ x,
                                                 const float* __restrict__ g,
                                                 const float* __restrict__ b,
                                                 float* __restrict__ out) {
    long row = blockIdx.x;
    const float4* xr = (const float4*)(x + row * D_);
    float4* orow = (float4*)(out + row * D_);
    int tid = threadIdx.x;
    float4 v = xr[tid];
    float s = v.x + v.y + v.z + v.w;
    float q = v.x * v.x + v.y * v.y + v.z * v.z + v.w * v.w;
    s = warp_sum(s);
    q = warp_sum(q);
    __shared__ float sh_s[8], sh_q[8];
    int w = tid >> 5, l = tid & 31;
    if (l == 0) { sh_s[w] = s; sh_q[w] = q; }
    __syncthreads();
    if (w == 0) {
        float ss = (l < 8) ? sh_s[l] : 0.f;
        float qq = (l < 8) ? sh_q[l] : 0.f;
        ss = warp_sum(ss);
        qq = warp_sum(qq);
        if (l == 0) { sh_s[0] = ss; sh_q[0] = qq; }
    }
    __syncthreads();
    float mu = sh_s[0] * (1.f / D_);
    float var = sh_q[0] * (1.f / D_) - mu * mu;
    float r = rsqrtf(var + 1e-5f);
    float4 gg = ((const float4*)g)[tid];
    float4 bb = ((const float4*)b)[tid];
    float4 o;
    o.x = (v.x - mu) * r * gg.x + bb.x;
    o.y = (v.y - mu) * r * gg.y + bb.y;
    o.z = (v.z - mu) * r * gg.z + bb.z;
    o.w = (v.w - mu) * r * gg.w + bb.w;
    orow[tid] = o;
}

// ==================== LayerNorm with bf16 hi/lo split output ====================
__global__ void __launch_bounds__(256) ln_split_kernel(const float* __restrict__ x,
                                                       const float* __restrict__ g,
                                                       const float* __restrict__ b,
                                                       __nv_bfloat16* __restrict__ hi,
                                                       __nv_bfloat16* __restrict__ lo) {
    long row = blockIdx.x;
    const float4* xr = (const float4*)(x + row * D_);
    int tid = threadIdx.x;
    float4 v = xr[tid];
    float s = v.x + v.y + v.z + v.w;
    float q = v.x * v.x + v.y * v.y + v.z * v.z + v.w * v.w;
    s = warp_sum(s);
    q = warp_sum(q);
    __shared__ float sh_s[8], sh_q[8];
    int w = tid >> 5, l = tid & 31;
    if (l == 0) { sh_s[w] = s; sh_q[w] = q; }
    __syncthreads();
    if (w == 0) {
        float ss = (l < 8) ? sh_s[l] : 0.f;
        float qq = (l < 8) ? sh_q[l] : 0.f;
        ss = warp_sum(ss);
        qq = warp_sum(qq);
        if (l == 0) { sh_s[0] = ss; sh_q[0] = qq; }
    }
    __syncthreads();
    float mu = sh_s[0] * (1.f / D_);
    float var = sh_q[0] * (1.f / D_) - mu * mu;
    float r = rsqrtf(var + 1e-5f);
    float4 gg = ((const float4*)g)[tid];
    float4 bb = ((const float4*)b)[tid];
    float o0 = (v.x - mu) * r * gg.x + bb.x;
    float o1 = (v.y - mu) * r * gg.y + bb.y;
    float o2 = (v.z - mu) * r * gg.z + bb.z;
    float o3 = (v.w - mu) * r * gg.w + bb.w;
    uint32_t h01, l01, h23, l23;
    split2(o0, o1, h01, l01);
    split2(o2, o3, h23, l23);
    ((uint2*)(hi + row * D_))[tid] = make_uint2(h01, h23);
    ((uint2*)(lo + row * D_))[tid] = make_uint2(l01, l23);
}

// ==================== fused weight split (all 4 weights, one launch) ==========
// tasks (float4 units): [0,131072) Wspec, [131072,262144) Wfrom,
//                       [262144,524288) W1, [524288,786432) W2
__global__ void __launch_bounds__(256) split_all_kernel(
    const float4* __restrict__ Wspec, const float4* __restrict__ Wfrom,
    const float4* __restrict__ W1, const float4* __restrict__ W2,
    uint2* __restrict__ WB) {        // packed hi/lo regions, uint2 = 4 bf16
    int i = blockIdx.x * 256 + threadIdx.x;
    const float4* src;
    long hioff, looff, idx;
    if (i < 131072) { src = Wspec; idx = i; hioff = 0L; looff = 131072L; }
    else if (i < 262144) { src = Wfrom; idx = i - 131072; hioff = 262144L; looff = 393216L; }
    else if (i < 524288) { src = W1; idx = i - 262144; hioff = 524288L; looff = 786432L; }
    else { src = W2; idx = i - 524288; hioff = 1048576L; looff = 1310720L; }
    float4 v = src[idx];
    uint32_t h01, l01, h23, l23;
    split2(v.x, v.y, h01, l01);
    split2(v.z, v.w, h23, l23);
    WB[hioff + idx] = make_uint2(h01, h23);
    WB[looff + idx] = make_uint2(l01, l23);
}

// ==================== bf16-split warp-MMA GEMM ====================
// C[m,n] = sum_k A[m,k]*W[n,k];  A,W as bf16 hi/lo. 256x128x32 tile,
// 512 threads (16 warps, 4m x 4n, warp tile 64x32), 3-stage cp.async.
// EPI: 0 = f32 out, 1 = bias+gelu -> bf16 hi/lo out, 2 = bias -> f32 out.
#define NSTAGE 3
#define A_PART 20480                  // 256 rows * 80B
#define B_PART 10240                  // 128 rows * 80B
#define STAGE_BYTES 61440             // AHI ALO BHI BLO
#define SMEM_GEMM (NSTAGE * STAGE_BYTES)

template <int EPI>
__global__ void __launch_bounds__(512, 1) gemm_mma(
    const __nv_bfloat16* __restrict__ Ahi, const __nv_bfloat16* __restrict__ Alo,
    const __nv_bfloat16* __restrict__ Bhi, const __nv_bfloat16* __restrict__ Blo,
    const float* __restrict__ bias,
    float* __restrict__ Cf,
    __nv_bfloat16* __restrict__ Chi, __nv_bfloat16* __restrict__ Clo,
    int N, int K) {
    extern __shared__ char sm[];
    const int tid = threadIdx.x;
    const int lane = tid & 31, w = tid >> 5;
    const int bm = blockIdx.y << 8, bn = blockIdx.x << 7;
    const int wm = (w & 3) << 6, wn = (w >> 2) << 5;   // 4m x 4n warps
    const uint32_t sbase = smem_u32(sm);

    float acc[4][4][4];
#pragma unroll
    for (int i = 0; i < 4; i++)
#pragma unroll
        for (int j = 0; j < 4; j++)
#pragma unroll
            for (int r = 0; r < 4; r++) acc[i][j][r] = 0.f;

    auto issue = [&](int kt, int s) {
        const int k0 = kt << 5;
        const uint32_t sst = sbase + s * STAGE_BYTES;
#pragma unroll
        for (int i = 0; i < 6; ++i) {
            int task = tid + (i << 9);             // 0..3071
            const __nv_bfloat16* base;
            long grow;
            uint32_t sa;
            if (task < 2048) {                     // A: 2 parts x 256 rows x 4
                int p = task >> 10;
                int lt = task & 1023;
                int row = lt >> 2, c = lt & 3;
                base = p ? Alo : Ahi;
                grow = (long)(bm + row) * K + k0 + (c << 3);
                sa = sst + p * A_PART + row * 80 + (c << 4);
            } else {                               // B: 2 parts x 128 rows x 4
                int t2 = task - 2048;
                int p = t2 >> 9;
                int lt = t2 & 511;
                int row = lt >> 2, c = lt & 3;
                base = p ? Blo : Bhi;
                grow = (long)(bn + row) * K + k0 + (c << 3);
                sa = sst + 2 * A_PART + p * B_PART + row * 80 + (c << 4);
            }
            CP_ASYNC16(sa, base + grow);
        }
        asm volatile("cp.async.commit_group;");
    };

    const int nk = K >> 5;
    issue(0, 0); issue(1, 1);

    const int lr = lane & 15;
    const int lkc = (lane >> 4) << 4;

    for (int kt = 0; kt < nk; ++kt) {
        asm volatile("cp.async.wait_group 1;");
        __syncthreads();
        int nxt = kt + NSTAGE - 1;
        if (nxt < nk) issue(nxt, nxt % NSTAGE);
        else asm volatile("cp.async.commit_group;");

        const uint32_t sst = sbase + (kt % NSTAGE) * STAGE_BYTES;
#pragma unroll
        for (int ks = 0; ks < 2; ++ks) {
            // B fragments resident: 4 nf x (hi,lo)
            uint32_t bh[4][2], bl[4][2];
#pragma unroll
            for (int g = 0; g < 2; ++g) {
                uint32_t bd = sst + 2 * A_PART + (wn + (g << 4) + lr) * 80 +
                              (ks << 5) + lkc;
                uint32_t t0, t1, t2, t3;
                LDSM4(t0, t1, t2, t3, bd);
                bh[2 * g][0] = t0; bh[2 * g][1] = t2;
                bh[2 * g + 1][0] = t1; bh[2 * g + 1][1] = t3;
                LDSM4(t0, t1, t2, t3, bd + B_PART);
                bl[2 * g][0] = t0; bl[2 * g][1] = t2;
                bl[2 * g + 1][0] = t1; bl[2 * g + 1][1] = t3;
            }
            // A fragments loaded per 16-row mf to bound register pressure
#pragma unroll
            for (int mf = 0; mf < 4; ++mf) {
                uint32_t ah[4], al[4];
                uint32_t ad = sst + (wm + (mf << 4) + lr) * 80 + (ks << 5) + lkc;
                LDSM4(ah[0], ah[1], ah[2], ah[3], ad);
                LDSM4(al[0], al[1], al[2], al[3], ad + A_PART);
                // pass-major: same-acc MMAs 4 apart
#pragma unroll
                for (int nf = 0; nf < 4; ++nf) MMA_BF16(acc[mf][nf], ah, bh[nf]);
#pragma unroll
                for (int nf = 0; nf < 4; ++nf) MMA_BF16(acc[mf][nf], ah, bl[nf]);
#pragma unroll
                for (int nf = 0; nf < 4; ++nf) MMA_BF16(acc[mf][nf], al, bh[nf]);
            }
        }
    }

    // epilogue
#pragma unroll
    for (int mf = 0; mf < 4; ++mf) {
#pragma unroll
        for (int h = 0; h < 2; ++h) {
            int row = bm + wm + (mf << 4) + (lane >> 2) + (h << 3);
#pragma unroll
            for (int nf = 0; nf < 4; ++nf) {
                int col = bn + wn + (nf << 3) + ((lane & 3) << 1);
                float v0 = acc[mf][nf][h * 2];
                float v1 = acc[mf][nf][h * 2 + 1];
                if (EPI >= 1) { v0 += bias[col]; v1 += bias[col + 1]; }
                if (EPI == 1) {
                    v0 = 0.5f * v0 * (1.f + erff(v0 * 0.70710678118654752f));
                    v1 = 0.5f * v1 * (1.f + erff(v1 * 0.70710678118654752f));
                    uint32_t hh, ll;
                    split2(v0, v1, hh, ll);
                    *(uint32_t*)(Chi + (long)row * N + col) = hh;
                    *(uint32_t*)(Clo + (long)row * N + col) = ll;
                } else {
                    *(float2*)(Cf + (long)row * N + col) = make_float2(v0, v1);
                }
            }
        }
    }
}

// ==================== SSM scan (== FFT conv; |A|<0.5, halo=64) ====================
__global__ void __launch_bounds__(256) scan_kernel(const float* __restrict__ spec,
                                                   const float* __restrict__ log_decay,
                                                   const float* __restrict__ freqs,
                                                   __nv_bfloat16* __restrict__ yhi,
                                                   __nv_bfloat16* __restrict__ ylo) {
    const int CHUNK = 128, HALO = 64, NCH = S_ / CHUNK;   // 32 chunks
    int id = blockIdx.x * blockDim.x + threadIdx.x;       // 32768 threads
    int f = id & (F_ - 1);
    int chunk = (id >> 8) & (NCH - 1);
    int b = id >> 13;

    float decay = 1.f / (1.f + expf(-log_decay[f]));
    float om = tanhf(freqs[f]) * 0.1f;
    float rr = cosf(om), ri = sinf(om);
    float Ar = decay * rr, Ai = decay * ri;

    int c0 = chunk * CHUNK, c1 = c0 + CHUNK;
    int t0 = c0 - HALO; if (t0 < 0) t0 = 0;

    const float* base = spec + (long)b * S_ * TWOF_;
    long ybase = (long)b * S_ * TWOF_;

    float yr = 0.f, yi = 0.f;
    for (int t = t0; t < c1; ++t) {
        float ur = base[(long)t * TWOF_ + f];
        float ui = base[(long)t * TWOF_ + F_ + f];
        float nyr = Ar * yr - Ai * yi + rr * ur - ri * ui;
        float nyi = Ar * yi + Ai * yr + rr * ui + ri * ur;
        yr = nyr; yi = nyi;
        if (t >= c0) {
            long ir = ybase + (long)t * TWOF_ + f;
            long ii = ir + F_;
            __nv_bfloat16 hr = __float2bfloat16_rn(yr);
            __nv_bfloat16 hi2 = __float2bfloat16_rn(yi);
            yhi[ir] = hr; ylo[ir] = __float2bfloat16_rn(yr - __bfloat162float(hr));
            yhi[ii] = hi2; ylo[ii] = __float2bfloat16_rn(yi - __bfloat162float(hi2));
        }
    }
}

// ==================== error / corrected fusion ====================
__global__ void zero_err_kernel() { g_errsum = 0.0; }

__global__ void __launch_bounds__(256) err_kernel(const float4* __restrict__ bu,
                                                  const float4* __restrict__ td,
                                                  const float* __restrict__ ewp,
                                                  float4* __restrict__ corr,
                                                  uint2* __restrict__ chi,
                                                  uint2* __restrict__ clo) {
    int i = blockIdx.x * 256 + threadIdx.x;
    float s = 1.f / (1.f + expf(-ewp[0]));
    float4 a = bu[i], t = td[i];
    float ex = fminf(fmaxf(a.x - t.x, -1.f), 1.f);
    float ey = fminf(fmaxf(a.y - t.y, -1.f), 1.f);
    float ez = fminf(fmaxf(a.z - t.z, -1.f), 1.f);
    float ew = fminf(fmaxf(a.w - t.w, -1.f), 1.f);
    float4 c;
    c.x = a.x - s * ex; c.y = a.y - s * ey;
    c.z = a.z - s * ez; c.w = a.w - s * ew;
    corr[i] = c;
    uint32_t h01, l01, h23, l23;
    split2(c.x, c.y, h01, l01);
    split2(c.z, c.w, h23, l23);
    chi[i] = make_uint2(h01, h23);
    clo[i] = make_uint2(l01, l23);
    float le = ex * ex + ey * ey + ez * ez + ew * ew;
    le = warp_sum(le);
    __shared__ float sh[8];
    int w = threadIdx.x >> 5, l = threadIdx.x & 31;
    if (l == 0) sh[w] = le;
    __syncthreads();
    if (threadIdx.x == 0) {
        float t2 = 0.f;
#pragma unroll
        for (int k = 0; k < 8; k++) t2 += sh[k];
        atomicAdd(&g_errsum, (double)t2);
    }
}

__global__ void fin_kernel(float* __restrict__ out) {
    double m = g_errsum * (1.0 / (double)BSD_);
    float v = (float)m;
    out[2L * BSD_] = fminf(fmaxf(v, 0.f), 1.f);
}

// ==================== launch ====================
extern "C" void kernel_launch(void* const* d_in, const int* in_sizes, int n_in,
                              void* d_out, int out_size) {
    const float* bu_in  = (const float*)d_in[0];
    const float* td     = (const float*)d_in[1];
    const float* Wspec  = (const float*)d_in[2];
    const float* logdec = (const float*)d_in[3];
    const float* freqs  = (const float*)d_in[4];
    const float* Wfrom  = (const float*)d_in[5];
    const float* ln1g   = (const float*)d_in[6];
    const float* ln1b   = (const float*)d_in[7];
    const float* W1     = (const float*)d_in[8];
    const float* b1     = (const float*)d_in[9];
    const float* W2     = (const float*)d_in[10];
    const float* b2     = (const float*)d_in[11];
    const float* ln2g   = (const float*)d_in[12];
    const float* ln2b   = (const float*)d_in[13];
    const float* ewt    = (const float*)d_in[14];
    float* out = (float*)d_out;

    void* sp; cudaGetSymbolAddress(&sp, g_scratch);
    void* wp; cudaGetSymbolAddress(&wp, g_wbuf);
    float* S0 = (float*)sp;
    __nv_bfloat16* WB = (__nv_bfloat16*)wp;

    // region A [0,16M): xn hi/lo, later corr hi/lo
    __nv_bfloat16* xnhi = (__nv_bfloat16*)(S0);
    __nv_bfloat16* xnlo = (__nv_bfloat16*)(S0 + 8388608L);
    // region B [16M,24M): spec f32, later h1hi
    float* spec = S0 + 16777216L;
    __nv_bfloat16* h1hi = (__nv_bfloat16*)(S0 + 16777216L);
    // region C [24M,32M): y hi/lo, later h1lo
    __nv_bfloat16* yhi = (__nv_bfloat16*)(S0 + 25165824L);
    __nv_bfloat16* ylo = (__nv_bfloat16*)(S0 + 29360128L);
    __nv_bfloat16* h1lo = (__nv_bfloat16*)(S0 + 25165824L);
    // region D [32M,48M): buv f32, later h2 f32
    float* buv = S0 + 33554432L;
    float* h2  = S0 + 33554432L;

    // weight hi/lo slots (uint2 index x 4 = bf16 index)
    __nv_bfloat16* wspechi = WB;                  // uint2 off 0
    __nv_bfloat16* wspeclo = WB + 524288L;        // 131072
    __nv_bfloat16* wfromhi = WB + 1048576L;       // 262144
    __nv_bfloat16* wfromlo = WB + 1572864L;       // 393216
    __nv_bfloat16* w1hi    = WB + 2097152L;       // 524288
    __nv_bfloat16* w1lo    = WB + 3145728L;       // 786432
    __nv_bfloat16* w2hi    = WB + 4194304L;       // 1048576
    __nv_bfloat16* w2lo    = WB + 5242880L;       // 1310720

    float* corrected = out;
    float* nextp = out + BSD_;

    cudaFuncSetAttribute(gemm_mma<0>, cudaFuncAttributeMaxDynamicSharedMemorySize, SMEM_GEMM);
    cudaFuncSetAttribute(gemm_mma<1>, cudaFuncAttributeMaxDynamicSharedMemorySize, SMEM_GEMM);
    cudaFuncSetAttribute(gemm_mma<2>, cudaFuncAttributeMaxDynamicSharedMemorySize, SMEM_GEMM);

    // fused weight split
    split_all_kernel<<<3072, 256>>>((const float4*)Wspec, (const float4*)Wfrom,
                                    (const float4*)W1, (const float4*)W2,
                                    (uint2*)WB);

    // 1. ln1 -> xn hi/lo
    ln_split_kernel<<<M_, 256>>>(bu_in, ln1g, ln1b, xnhi, xnlo);
    // 2. spectral = xn @ Wspec^T [16384,512], K=1024
    gemm_mma<0><<<dim3(4, 64), 512, SMEM_GEMM>>>(xnhi, xnlo, wspechi, wspeclo,
                                                 nullptr, spec, nullptr, nullptr,
                                                 512, 1024);
    // 3. scan -> y hi/lo
    scan_kernel<<<128, 256>>>(spec, logdec, freqs, yhi, ylo);
    // 4. bu_repr = y @ Wfrom^T [16384,1024], K=512
    gemm_mma<0><<<dim3(8, 64), 512, SMEM_GEMM>>>(yhi, ylo, wfromhi, wfromlo,
                                                 nullptr, buv, nullptr, nullptr,
                                                 1024, 512);
    // 5. error/corrected + mean(e^2), corr hi/lo for next GEMM
    zero_err_kernel<<<1, 1>>>();
    err_kernel<<<16384, 256>>>((const float4*)buv, (const float4*)td, ewt,
                               (float4*)corrected, (uint2*)xnhi, (uint2*)xnlo);
    fin_kernel<<<1, 1>>>(out);
    // 6. h1 = gelu(corr @ W1^T + b1) -> bf16 hi/lo
    gemm_mma<1><<<dim3(8, 64), 512, SMEM_GEMM>>>(xnhi, xnlo, w1hi, w1lo, b1,
                                                 nullptr, h1hi, h1lo, 1024, 1024);
    // 7. h2 = h1 @ W2^T + b2 -> f32
    gemm_mma<2><<<dim3(8, 64), 512, SMEM_GEMM>>>(h1hi, h1lo, w2hi, w2lo, b2,
                                                 h2, nullptr, nullptr, 1024, 1024);
    // 8. next_prediction = ln2(h2)
    ln_kernel<<<M_, 256>>>(h2, ln2g, ln2b, nextp);
}

// round 13
// speedup vs baseline: 2.1614x; 1.0109x over previous
#include <cuda_runtime.h>
#include <cuda_bf16.h>
#include <cstdint>

// Problem constants (fixed shapes)
#define B_ 4
#define S_ 4096
#define D_ 1024
#define F_ 256
#define M_ 16384
#define BSD_ 16777216L
#define TWOF_ 512

// -------- scratch (no cudaMalloc allowed) --------
__device__ float g_scratch[50331648];
__device__ __nv_bfloat16 g_wbuf[6291456];   // hi/lo bf16 weights (12MB)
__device__ double g_errsum;

// ==================== helpers ====================
__device__ __forceinline__ float warp_sum(float v) {
#pragma unroll
    for (int o = 16; o; o >>= 1) v += __shfl_xor_sync(0xffffffffu, v, o);
    return v;
}

__device__ __forceinline__ uint32_t smem_u32(const void* p) {
    uint32_t a;
    asm("{ .reg .u64 t; cvta.to.shared.u64 t, %1; cvt.u32.u64 %0, t; }"
        : "=r"(a) : "l"(p));
    return a;
}

__device__ __forceinline__ void split2(float a, float b, uint32_t& h, uint32_t& l) {
    __nv_bfloat162 hh = __floats2bfloat162_rn(a, b);
    float ra = a - __low2float(hh);
    float rb = b - __high2float(hh);
    __nv_bfloat162 ll = __floats2bfloat162_rn(ra, rb);
    h = *reinterpret_cast<uint32_t*>(&hh);
    l = *reinterpret_cast<uint32_t*>(&ll);
}

#define LDSM4(r0, r1, r2, r3, a) \
    asm volatile("ldmatrix.sync.aligned.m8n8.x4.shared.b16 {%0,%1,%2,%3}, [%4];" \
                 : "=r"(r0), "=r"(r1), "=r"(r2), "=r"(r3) : "r"(a))

#define MMA_BF16(d, a, b) \
    asm volatile("mma.sync.aligned.m16n8k16.row.col.f32.bf16.bf16.f32 " \
                 "{%0,%1,%2,%3}, {%4,%5,%6,%7}, {%8,%9}, {%0,%1,%2,%3};" \
                 : "+f"((d)[0]), "+f"((d)[1]), "+f"((d)[2]), "+f"((d)[3]) \
                 : "r"((a)[0]), "r"((a)[1]), "r"((a)[2]), "r"((a)[3]), \
                   "r"((b)[0]), "r"((b)[1]))

#define CP_ASYNC16(s, g) \
    asm volatile("cp.async.cg.shared.global [%0], [%1], 16;" :: "r"(s), "l"(g))

// ==================== LayerNorm (f32 out) ====================
__global__ void __launch_bounds__(256) ln_kernel(const float* __restrict__ x,
                                                 const float* __restrict__ g,
                                                 const float* __restrict__ b,
                                                 float* __restrict__ out) {
    long row = blockIdx.x;
    const float4* xr = (const float4*)(x + row * D_);
    float4* orow = (float4*)(out + row * D_);
    int tid = threadIdx.x;
    float4 v = xr[tid];
    float s = v.x + v.y + v.z + v.w;
    float q = v.x * v.x + v.y * v.y + v.z * v.z + v.w * v.w;
    s = warp_sum(s);
    q = warp_sum(q);
    __shared__ float sh_s[8], sh_q[8];
    int w = tid >> 5, l = tid & 31;
    if (l == 0) { sh_s[w] = s; sh_q[w] = q; }
    __syncthreads();
    if (w == 0) {
        float ss = (l < 8) ? sh_s[l] : 0.f;
        float qq = (l < 8) ? sh_q[l] : 0.f;
        ss = warp_sum(ss);
        qq = warp_sum(qq);
        if (l == 0) { sh_s[0] = ss; sh_q[0] = qq; }
    }
    __syncthreads();
    float mu = sh_s[0] * (1.f / D_);
    float var = sh_q[0] * (1.f / D_) - mu * mu;
    float r = rsqrtf(var + 1e-5f);
    float4 gg = ((const float4*)g)[tid];
    float4 bb = ((const float4*)b)[tid];
    float4 o;
    o.x = (v.x - mu) * r * gg.x + bb.x;
    o.y = (v.y - mu) * r * gg.y + bb.y;
    o.z = (v.z - mu) * r * gg.z + bb.z;
    o.w = (v.w - mu) * r * gg.w + bb.w;
    orow[tid] = o;
}

// ==================== LayerNorm with bf16 hi/lo split output ====================
__global__ void __launch_bounds__(256) ln_split_kernel(const float* __restrict__ x,
                                                       const float* __restrict__ g,
                                                       const float* __restrict__ b,
                                                       __nv_bfloat16* __restrict__ hi,
                                                       __nv_bfloat16* __restrict__ lo) {
    long row = blockIdx.x;
    const float4* xr = (const float4*)(x + row * D_);
    int tid = threadIdx.x;
    float4 v = xr[tid];
    float s = v.x + v.y + v.z + v.w;
    float q = v.x * v.x + v.y * v.y + v.z * v.z + v.w * v.w;
    s = warp_sum(s);
    q = warp_sum(q);
    __shared__ float sh_s[8], sh_q[8];
    int w = tid >> 5, l = tid & 31;
    if (l == 0) { sh_s[w] = s; sh_q[w] = q; }
    __syncthreads();
    if (w == 0) {
        float ss = (l < 8) ? sh_s[l] : 0.f;
        float qq = (l < 8) ? sh_q[l] : 0.f;
        ss = warp_sum(ss);
        qq = warp_sum(qq);
        if (l == 0) { sh_s[0] = ss; sh_q[0] = qq; }
    }
    __syncthreads();
    float mu = sh_s[0] * (1.f / D_);
    float var = sh_q[0] * (1.f / D_) - mu * mu;
    float r = rsqrtf(var + 1e-5f);
    float4 gg = ((const float4*)g)[tid];
    float4 bb = ((const float4*)b)[tid];
    float o0 = (v.x - mu) * r * gg.x + bb.x;
    float o1 = (v.y - mu) * r * gg.y + bb.y;
    float o2 = (v.z - mu) * r * gg.z + bb.z;
    float o3 = (v.w - mu) * r * gg.w + bb.w;
    uint32_t h01, l01, h23, l23;
    split2(o0, o1, h01, l01);
    split2(o2, o3, h23, l23);
    ((uint2*)(hi + row * D_))[tid] = make_uint2(h01, h23);
    ((uint2*)(lo + row * D_))[tid] = make_uint2(l01, l23);
}

// ==================== fused weight split ====================
__global__ void __launch_bounds__(256) split_all_kernel(
    const float4* __restrict__ Wspec, const float4* __restrict__ Wfrom,
    const float4* __restrict__ W1, const float4* __restrict__ W2,
    uint2* __restrict__ WB) {
    int i = blockIdx.x * 256 + threadIdx.x;
    const float4* src;
    long hioff, looff, idx;
    if (i < 131072) { src = Wspec; idx = i; hioff = 0L; looff = 131072L; }
    else if (i < 262144) { src = Wfrom; idx = i - 131072; hioff = 262144L; looff = 393216L; }
    else if (i < 524288) { src = W1; idx = i - 262144; hioff = 524288L; looff = 786432L; }
    else { src = W2; idx = i - 524288; hioff = 1048576L; looff = 1310720L; }
    float4 v = src[idx];
    uint32_t h01, l01, h23, l23;
    split2(v.x, v.y, h01, l01);
    split2(v.z, v.w, h23, l23);
    WB[hioff + idx] = make_uint2(h01, h23);
    WB[looff + idx] = make_uint2(l01, l23);
}

// ==================== bf16-split warp-MMA GEMM ====================
// C[m,n] = sum_k A[m,k]*W[n,k];  A,W as bf16 hi/lo. 256x128x32 tile,
// 512 threads (16 warps, 4m x 4n), 3-stage cp.async.
// EPI: 0 = f32 out; 1 = bias+gelu -> bf16 hi/lo; 2 = bias -> f32;
//      3 = predictive-coding error fusion (corrected f32 + hi/lo + sum e^2).
#define NSTAGE 3
#define A_PART 20480
#define B_PART 10240
#define STAGE_BYTES 61440
#define SMEM_GEMM (NSTAGE * STAGE_BYTES)

template <int EPI>
__global__ void __launch_bounds__(512, 1) gemm_mma(
    const __nv_bfloat16* __restrict__ Ahi, const __nv_bfloat16* __restrict__ Alo,
    const __nv_bfloat16* __restrict__ Bhi, const __nv_bfloat16* __restrict__ Blo,
    const float* __restrict__ bias,
    float* __restrict__ Cf,
    __nv_bfloat16* __restrict__ Chi, __nv_bfloat16* __restrict__ Clo,
    const float* __restrict__ td, const float* __restrict__ ewp,
    int N, int K) {
    extern __shared__ char sm[];
    const int tid = threadIdx.x;
    const int lane = tid & 31, w = tid >> 5;
    const int bm = blockIdx.y << 8, bn = blockIdx.x << 7;
    const int wm = (w & 3) << 6, wn = (w >> 2) << 5;
    const uint32_t sbase = smem_u32(sm);

    float acc[4][4][4];
#pragma unroll
    for (int i = 0; i < 4; i++)
#pragma unroll
        for (int j = 0; j < 4; j++)
#pragma unroll
            for (int r = 0; r < 4; r++) acc[i][j][r] = 0.f;

    // precompute per-thread cp.async source pointers and smem offsets
    const __nv_bfloat16* gp[6];
    uint32_t so[6];
#pragma unroll
    for (int i = 0; i < 6; ++i) {
        int task = tid + (i << 9);
        if (task < 2048) {
            int p = task >> 10;
            int lt = task & 1023;
            int row = lt >> 2, c = lt & 3;
            gp[i] = (p ? Alo : Ahi) + (long)(bm + row) * K + (c << 3);
            so[i] = p * A_PART + row * 80 + (c << 4);
        } else {
            int t2 = task - 2048;
            int p = t2 >> 9;
            int lt = t2 & 511;
            int row = lt >> 2, c = lt & 3;
            gp[i] = (p ? Blo : Bhi) + (long)(bn + row) * K + (c << 3);
            so[i] = 2 * A_PART + p * B_PART + row * 80 + (c << 4);
        }
    }

    auto issue = [&](int kt, int s) {
        const uint32_t sst = sbase + s * STAGE_BYTES;
        const int ke = kt << 5;
#pragma unroll
        for (int i = 0; i < 6; ++i) CP_ASYNC16(sst + so[i], gp[i] + ke);
        asm volatile("cp.async.commit_group;");
    };

    const int nk = K >> 5;
    issue(0, 0); issue(1, 1);

    const int lr = lane & 15;
    const int lkc = (lane >> 4) << 4;

    for (int kt = 0; kt < nk; ++kt) {
        asm volatile("cp.async.wait_group 1;");
        __syncthreads();
        int nxt = kt + NSTAGE - 1;
        if (nxt < nk) issue(nxt, nxt % NSTAGE);
        else asm volatile("cp.async.commit_group;");

        const uint32_t sst = sbase + (kt % NSTAGE) * STAGE_BYTES;
#pragma unroll
        for (int ks = 0; ks < 2; ++ks) {
            uint32_t bh[4][2], bl[4][2];
#pragma unroll
            for (int g = 0; g < 2; ++g) {
                uint32_t bd = sst + 2 * A_PART + (wn + (g << 4) + lr) * 80 +
                              (ks << 5) + lkc;
                uint32_t t0, t1, t2, t3;
                LDSM4(t0, t1, t2, t3, bd);
                bh[2 * g][0] = t0; bh[2 * g][1] = t2;
                bh[2 * g + 1][0] = t1; bh[2 * g + 1][1] = t3;
                LDSM4(t0, t1, t2, t3, bd + B_PART);
                bl[2 * g][0] = t0; bl[2 * g][1] = t2;
                bl[2 * g + 1][0] = t1; bl[2 * g + 1][1] = t3;
            }
#pragma unroll
            for (int mf = 0; mf < 4; ++mf) {
                uint32_t ah[4], al[4];
                uint32_t ad = sst + (wm + (mf << 4) + lr) * 80 + (ks << 5) + lkc;
                LDSM4(ah[0], ah[1], ah[2], ah[3], ad);
                LDSM4(al[0], al[1], al[2], al[3], ad + A_PART);
#pragma unroll
                for (int nf = 0; nf < 4; ++nf) MMA_BF16(acc[mf][nf], ah, bh[nf]);
#pragma unroll
                for (int nf = 0; nf < 4; ++nf) MMA_BF16(acc[mf][nf], ah, bl[nf]);
#pragma unroll
                for (int nf = 0; nf < 4; ++nf) MMA_BF16(acc[mf][nf], al, bh[nf]);
            }
        }
    }

    // ---------------- epilogue ----------------
    float esum = 0.f;
    float sw = 0.f;
    if (EPI == 3) sw = 1.f / (1.f + expf(-ewp[0]));
#pragma unroll
    for (int mf = 0; mf < 4; ++mf) {
#pragma unroll
        for (int h = 0; h < 2; ++h) {
            int row = bm + wm + (mf << 4) + (lane >> 2) + (h << 3);
#pragma unroll
            for (int nf = 0; nf < 4; ++nf) {
                int col = bn + wn + (nf << 3) + ((lane & 3) << 1);
                float v0 = acc[mf][nf][h * 2];
                float v1 = acc[mf][nf][h * 2 + 1];
                if (EPI == 1 || EPI == 2) { v0 += bias[col]; v1 += bias[col + 1]; }
                if (EPI == 1) {
                    v0 = 0.5f * v0 * (1.f + erff(v0 * 0.70710678118654752f));
                    v1 = 0.5f * v1 * (1.f + erff(v1 * 0.70710678118654752f));
                    uint32_t hh, ll;
                    split2(v0, v1, hh, ll);
                    *(uint32_t*)(Chi + (long)row * N + col) = hh;
                    *(uint32_t*)(Clo + (long)row * N + col) = ll;
                } else if (EPI == 3) {
                    float2 t = *(const float2*)(td + (long)row * N + col);
                    float e0 = fminf(fmaxf(v0 - t.x, -1.f), 1.f);
                    float e1 = fminf(fmaxf(v1 - t.y, -1.f), 1.f);
                    float c0 = v0 - sw * e0;
                    float c1 = v1 - sw * e1;
                    esum += e0 * e0 + e1 * e1;
                    *(float2*)(Cf + (long)row * N + col) = make_float2(c0, c1);
                    uint32_t hh, ll;
                    split2(c0, c1, hh, ll);
                    *(uint32_t*)(Chi + (long)row * N + col) = hh;
                    *(uint32_t*)(Clo + (long)row * N + col) = ll;
                } else {
                    *(float2*)(Cf + (long)row * N + col) = make_float2(v0, v1);
                }
            }
        }
    }
    if (EPI == 3) {
        esum = warp_sum(esum);
        __shared__ float shred[16];
        if (lane == 0) shred[w] = esum;
        __syncthreads();
        if (tid == 0) {
            float t = 0.f;
#pragma unroll
            for (int k = 0; k < 16; ++k) t += shred[k];
            atomicAdd(&g_errsum, (double)t);
        }
    }
}

// ==================== SSM scan (== FFT conv; |A|<0.5, halo=64) ====================
__global__ void __launch_bounds__(256) scan_kernel(const float* __restrict__ spec,
                                                   const float* __restrict__ log_decay,
                                                   const float* __restrict__ freqs,
                                                   __nv_bfloat16* __restrict__ yhi,
                                                   __nv_bfloat16* __restrict__ ylo) {
    const int CHUNK = 64, HALO = 64, NCH = S_ / CHUNK;    // 64 chunks
    int id = blockIdx.x * blockDim.x + threadIdx.x;       // 65536 threads
    int f = id & (F_ - 1);
    int chunk = (id >> 8) & (NCH - 1);
    int b = id >> 14;

    float decay = 1.f / (1.f + expf(-log_decay[f]));
    float om = tanhf(freqs[f]) * 0.1f;
    float rr = cosf(om), ri = sinf(om);
    float Ar = decay * rr, Ai = decay * ri;

    int c0 = chunk * CHUNK, c1 = c0 + CHUNK;
    int t0 = c0 - HALO; if (t0 < 0) t0 = 0;

    const float* base = spec + (long)b * S_ * TWOF_;
    long ybase = (long)b * S_ * TWOF_;

    float yr = 0.f, yi = 0.f;
    for (int t = t0; t < c1; ++t) {
        float ur = base[(long)t * TWOF_ + f];
        float ui = base[(long)t * TWOF_ + F_ + f];
        float nyr = Ar * yr - Ai * yi + rr * ur - ri * ui;
        float nyi = Ar * yi + Ai * yr + rr * ui + ri * ur;
        yr = nyr; yi = nyi;
        if (t >= c0) {
            long ir = ybase + (long)t * TWOF_ + f;
            long ii = ir + F_;
            __nv_bfloat16 hr = __float2bfloat16_rn(yr);
            __nv_bfloat16 hi2 = __float2bfloat16_rn(yi);
            yhi[ir] = hr; ylo[ir] = __float2bfloat16_rn(yr - __bfloat162float(hr));
            yhi[ii] = hi2; ylo[ii] = __float2bfloat16_rn(yi - __bfloat162float(hi2));
        }
    }
}

// ==================== scalar kernels ====================
__global__ void zero_err_kernel() { g_errsum = 0.0; }

__global__ void fin_kernel(float* __restrict__ out) {
    double m = g_errsum * (1.0 / (double)BSD_);
    float v = (float)m;
    out[2L * BSD_] = fminf(fmaxf(v, 0.f), 1.f);
}

// ==================== launch ====================
extern "C" void kernel_launch(void* const* d_in, const int* in_sizes, int n_in,
                              void* d_out, int out_size) {
    const float* bu_in  = (const float*)d_in[0];
    const float* td     = (const float*)d_in[1];
    const float* Wspec  = (const float*)d_in[2];
    const float* logdec = (const float*)d_in[3];
    const float* freqs  = (const float*)d_in[4];
    const float* Wfrom  = (const float*)d_in[5];
    const float* ln1g   = (const float*)d_in[6];
    const float* ln1b   = (const float*)d_in[7];
    const float* W1     = (const float*)d_in[8];
    const float* b1     = (const float*)d_in[9];
    const float* W2     = (const float*)d_in[10];
    const float* b2     = (const float*)d_in[11];
    const float* ln2g   = (const float*)d_in[12];
    const float* ln2b   = (const float*)d_in[13];
    const float* ewt    = (const float*)d_in[14];
    float* out = (float*)d_out;

    void* sp; cudaGetSymbolAddress(&sp, g_scratch);
    void* wp; cudaGetSymbolAddress(&wp, g_wbuf);
    float* S0 = (float*)sp;
    __nv_bfloat16* WB = (__nv_bfloat16*)wp;

    // region A [0,16M): xn hi/lo, later corr hi/lo
    __nv_bfloat16* xnhi = (__nv_bfloat16*)(S0);
    __nv_bfloat16* xnlo = (__nv_bfloat16*)(S0 + 8388608L);
    // region B [16M,24M): spec f32, later h1hi
    float* spec = S0 + 16777216L;
    __nv_bfloat16* h1hi = (__nv_bfloat16*)(S0 + 16777216L);
    // region C [24M,32M): y hi/lo, later h1lo
    __nv_bfloat16* yhi = (__nv_bfloat16*)(S0 + 25165824L);
    __nv_bfloat16* ylo = (__nv_bfloat16*)(S0 + 29360128L);
    __nv_bfloat16* h1lo = (__nv_bfloat16*)(S0 + 25165824L);
    // region D [32M,48M): h2 f32
    float* h2  = S0 + 33554432L;

    __nv_bfloat16* wspechi = WB;
    __nv_bfloat16* wspeclo = WB + 524288L;
    __nv_bfloat16* wfromhi = WB + 1048576L;
    __nv_bfloat16* wfromlo = WB + 1572864L;
    __nv_bfloat16* w1hi    = WB + 2097152L;
    __nv_bfloat16* w1lo    = WB + 3145728L;
    __nv_bfloat16* w2hi    = WB + 4194304L;
    __nv_bfloat16* w2lo    = WB + 5242880L;

    float* corrected = out;
    float* nextp = out + BSD_;

    cudaFuncSetAttribute(gemm_mma<0>, cudaFuncAttributeMaxDynamicSharedMemorySize, SMEM_GEMM);
    cudaFuncSetAttribute(gemm_mma<1>, cudaFuncAttributeMaxDynamicSharedMemorySize, SMEM_GEMM);
    cudaFuncSetAttribute(gemm_mma<2>, cudaFuncAttributeMaxDynamicSharedMemorySize, SMEM_GEMM);
    cudaFuncSetAttribute(gemm_mma<3>, cudaFuncAttributeMaxDynamicSharedMemorySize, SMEM_GEMM);

    // fused weight split
    split_all_kernel<<<3072, 256>>>((const float4*)Wspec, (const float4*)Wfrom,
                                    (const float4*)W1, (const float4*)W2,
                                    (uint2*)WB);

    // 1. ln1 -> xn hi/lo
    ln_split_kernel<<<M_, 256>>>(bu_in, ln1g, ln1b, xnhi, xnlo);
    // 2. spectral = xn @ Wspec^T [16384,512], K=1024
    gemm_mma<0><<<dim3(4, 64), 512, SMEM_GEMM>>>(xnhi, xnlo, wspechi, wspeclo,
                                                 nullptr, spec, nullptr, nullptr,
                                                 nullptr, nullptr, 512, 1024);
    // 3. scan -> y hi/lo
    scan_kernel<<<256, 256>>>(spec, logdec, freqs, yhi, ylo);
    // 4. bu_repr = y @ Wfrom^T fused with error/corrected/mean(e^2)
    zero_err_kernel<<<1, 1>>>();
    gemm_mma<3><<<dim3(8, 64), 512, SMEM_GEMM>>>(yhi, ylo, wfromhi, wfromlo,
                                                 nullptr, corrected, xnhi, xnlo,
                                                 td, ewt, 1024, 512);
    fin_kernel<<<1, 1>>>(out);
    // 5. h1 = gelu(corr @ W1^T + b1) -> bf16 hi/lo
    gemm_mma<1><<<dim3(8, 64), 512, SMEM_GEMM>>>(xnhi, xnlo, w1hi, w1lo, b1,
                                                 nullptr, h1hi, h1lo,
                                                 nullptr, nullptr, 1024, 1024);
    // 6. h2 = h1 @ W2^T + b2 -> f32
    gemm_mma<2><<<dim3(8, 64), 512, SMEM_GEMM>>>(h1hi, h1lo, w2hi, w2lo, b2,
                                                 h2, nullptr, nullptr,
                                                 nullptr, nullptr, 1024, 1024);
    // 7. next_prediction = ln2(h2)
    ln_kernel<<<M_, 256>>>(h2, ln2g, ln2b, nextp);
}